// round 3
// baseline (speedup 1.0000x reference)
#include <cuda_runtime.h>

// Reference math: dx = 0  =>  s^2 = -dt^2 <= 0 everywhere  =>  spacelike_mask == 0
// => penalty == 0 => total_loss = base_loss + 0.01 * 0 = base_loss (bit-exact in fp32).
// attn_weights (d_in[0], ~302M floats) is dead input.
//
// R3: converged configuration — captured graph is a single 4-byte D2D memcpy
// node (beat the 1-thread kernel node 4.61 vs 4.86 µs in R2). This is the
// structural floor: one mandatory d_out write, 4 bytes, no removable work.
// This round confirms run-to-run variance of that floor.

extern "C" void kernel_launch(void* const* d_in, const int* in_sizes, int n_in,
                              void* d_out, int out_size) {
    // d_in[1] = base_loss scalar f32; d_out[0] = total_loss f32
    cudaMemcpyAsync(d_out, d_in[1], sizeof(float),
                    cudaMemcpyDefault, (cudaStream_t)0);
}